// round 17
// baseline (speedup 1.0000x reference)
#include <cuda_runtime.h>
#include <cuda_bf16.h>
#include <cstdint>

typedef unsigned int uint32;

#define TT    2048
#define BB    128
#define IN_D  256
#define HH    256
#define G3    768
#define NBLK  96
#define CHUNK_PER_T (3 * G3 * BB)      /* floats per timestep of GX */

// ---------------- static device scratch ----------------
__device__ float g_GXa[(size_t)1024 * CHUNK_PER_T];      // t in [0,1024)
__device__ float g_GXb[(size_t)1024 * CHUNK_PER_T];      // t in [1024,2048)
__device__ unsigned short g_Xhi[(size_t)TT * BB * IN_D]; // x split  [t][b][i]
__device__ unsigned short g_Xlo[(size_t)TT * BB * IN_D];
__device__ unsigned short g_WxBhi[3 * G3 * IN_D];        // Wx^T split [n][k]
__device__ unsigned short g_WxBlo[3 * G3 * IN_D];
__device__ unsigned short g_Hh[3][3][BB][HH];            // h bf16 hi, TRIPLE-buffered
__device__ unsigned short g_Hl[3][3][BB][HH];            // h bf16 lo
__device__ float g_Hfin[3][BB][HH];                      // final exact h
__device__ unsigned g_gbar[12 * 32];                     // init barriers (per group)
__device__ unsigned g_cnt[12 * 8 * 32];                  // per (group, slice) publish ctr
__device__ unsigned g_done;

__device__ __forceinline__ float* GXptr(int t) {
    return (t < 1024) ? (g_GXa + (size_t)t * CHUNK_PER_T)
                      : (g_GXb + (size_t)(t - 1024) * CHUNK_PER_T);
}

// ---------------- bf16 split helpers ----------------
__device__ __forceinline__ unsigned short f2b(float x) {
    return __bfloat16_as_ushort(__float2bfloat16(x));
}
__device__ __forceinline__ float b2f(unsigned short u) {
    return __bfloat162float(__ushort_as_bfloat16(u));
}
__device__ __forceinline__ void bsplit(float x, unsigned short& hi, unsigned short& lo) {
    hi = f2b(x);
    lo = f2b(x - b2f(hi));
}

// ---------------- mma / ldmatrix ----------------
__device__ __forceinline__ void mma16816(float* d, const uint32* a, uint32 b0, uint32 b1) {
    asm volatile(
        "mma.sync.aligned.m16n8k16.row.col.f32.bf16.bf16.f32 "
        "{%0,%1,%2,%3},{%4,%5,%6,%7},{%8,%9},{%0,%1,%2,%3};\n"
        : "+f"(d[0]), "+f"(d[1]), "+f"(d[2]), "+f"(d[3])
        : "r"(a[0]), "r"(a[1]), "r"(a[2]), "r"(a[3]), "r"(b0), "r"(b1));
}
__device__ __forceinline__ void ldsm4(uint32* r, const void* p) {
    uint32 a = (uint32)__cvta_generic_to_shared(p);
    asm volatile("ldmatrix.sync.aligned.m8n8.x4.shared.b16 {%0,%1,%2,%3},[%4];\n"
                 : "=r"(r[0]), "=r"(r[1]), "=r"(r[2]), "=r"(r[3]) : "r"(a));
}
__device__ __forceinline__ unsigned volread(const unsigned* p) {
    unsigned v;
    asm volatile("ld.volatile.global.u32 %0, [%1];" : "=r"(v) : "l"(p) : "memory");
    return v;
}

// ======================================================================
// Split x -> bf16 hi/lo, layout [t][b][i]. grid 2048, 256 thr.
// ======================================================================
__global__ __launch_bounds__(256) void k_split_x(const float* __restrict__ x)
{
    const int t = blockIdx.x;
    #pragma unroll 4
    for (int p = 0; p < 32; ++p) {
        int idx = threadIdx.x + p * 256;
        int b = idx >> 6, i4 = idx & 63;
        float4 v = __ldg((const float4*)(x + ((size_t)b * TT + t) * IN_D + i4 * 4));
        unsigned short h0, l0, h1, l1, h2, l2, h3, l3;
        bsplit(v.x, h0, l0); bsplit(v.y, h1, l1);
        bsplit(v.z, h2, l2); bsplit(v.w, h3, l3);
        uint2 hv = make_uint2((uint32)h0 | ((uint32)h1 << 16),
                              (uint32)h2 | ((uint32)h3 << 16));
        uint2 lv = make_uint2((uint32)l0 | ((uint32)l1 << 16),
                              (uint32)l2 | ((uint32)l3 << 16));
        size_t o = ((size_t)t * BB + b) * IN_D + i4 * 4;
        *(uint2*)(g_Xhi + o) = hv;
        *(uint2*)(g_Xlo + o) = lv;
    }
}

// Split + transpose Wx -> [n = kk*768 + o][k]. grid 2304, 256 thr.
__global__ __launch_bounds__(256) void k_split_wx(const float* __restrict__ Wx)
{
    const int n = blockIdx.x;
    const int kk = n / G3, o = n - kk * G3;
    const int k = threadIdx.x;
    float v = __ldg(Wx + ((size_t)kk * IN_D + k) * G3 + o);
    unsigned short hi, lo; bsplit(v, hi, lo);
    g_WxBhi[(size_t)n * IN_D + k] = hi;
    g_WxBlo[(size_t)n * IN_D + k] = lo;
}

// ======================================================================
// Kernel 1: GX[t][kk][b][o] = x_t @ Wx + bx  (unchanged, proven)
// ======================================================================
#define KPB 72

__global__ __launch_bounds__(256) void k_xgemm(const float* __restrict__ bx)
{
    extern __shared__ unsigned short smx[];
    unsigned short* AHi = smx;
    unsigned short* ALo = smx + 128 * KPB;
    unsigned short* BHi = smx + 2 * 128 * KPB;
    unsigned short* BLo = BHi + 64 * KPB;
    float* Ds = (float*)smx;

    const int t   = blockIdx.y;
    const int kk  = blockIdx.x / 12;
    const int o0  = (blockIdx.x % 12) * 64;
    const int tid = threadIdx.x;
    const int w = tid >> 5, lane = tid & 31;
    const int g = lane >> 2, tig = lane & 3;
    const int wm = w & 3, wn = w >> 2;
    const int lr = lane & 15, lc = (lane >> 4) * 8;
    const int br = ((lane >> 4) & 1) * 8 + (lane & 7);
    const int bc = ((lane >> 3) & 1) * 8;

    float acc[2][4][4];
    #pragma unroll
    for (int mt = 0; mt < 2; ++mt)
        #pragma unroll
        for (int nt = 0; nt < 4; ++nt)
            #pragma unroll
            for (int c = 0; c < 4; ++c) acc[mt][nt][c] = 0.f;

    for (int kc = 0; kc < 4; ++kc) {
        #pragma unroll
        for (int p = 0; p < 4; ++p) {
            int idx = tid + p * 256;
            int b = idx >> 3, k8 = idx & 7;
            size_t go = ((size_t)t * BB + b) * IN_D + kc * 64 + k8 * 8;
            *(uint4*)(AHi + b * KPB + k8 * 8) = __ldg((const uint4*)(g_Xhi + go));
            *(uint4*)(ALo + b * KPB + k8 * 8) = __ldg((const uint4*)(g_Xlo + go));
        }
        #pragma unroll
        for (int p = 0; p < 2; ++p) {
            int idx = tid + p * 256;
            int n = idx >> 3, k8 = idx & 7;
            size_t go = (size_t)(kk * G3 + o0 + n) * IN_D + kc * 64 + k8 * 8;
            *(uint4*)(BHi + n * KPB + k8 * 8) = __ldg((const uint4*)(g_WxBhi + go));
            *(uint4*)(BLo + n * KPB + k8 * 8) = __ldg((const uint4*)(g_WxBlo + go));
        }
        __syncthreads();

        #pragma unroll
        for (int kt = 0; kt < 4; ++kt) {
            int k0 = kt * 16;
            uint32 ah[2][4], al[2][4];
            #pragma unroll
            for (int mt = 0; mt < 2; ++mt) {
                int R = wm * 32 + mt * 16 + lr;
                ldsm4(ah[mt], AHi + R * KPB + k0 + lc);
                ldsm4(al[mt], ALo + R * KPB + k0 + lc);
            }
            uint32 bh[4][2], bl[4][2];
            #pragma unroll
            for (int p = 0; p < 2; ++p) {
                uint32 r4[4];
                int R = wn * 32 + p * 16 + br;
                ldsm4(r4, BHi + R * KPB + k0 + bc);
                bh[2*p][0] = r4[0]; bh[2*p][1] = r4[1];
                bh[2*p+1][0] = r4[2]; bh[2*p+1][1] = r4[3];
                ldsm4(r4, BLo + R * KPB + k0 + bc);
                bl[2*p][0] = r4[0]; bl[2*p][1] = r4[1];
                bl[2*p+1][0] = r4[2]; bl[2*p+1][1] = r4[3];
            }
            #pragma unroll
            for (int mt = 0; mt < 2; ++mt)
                #pragma unroll
                for (int nt = 0; nt < 4; ++nt) {
                    mma16816(acc[mt][nt], ah[mt], bh[nt][0], bh[nt][1]);
                    mma16816(acc[mt][nt], ah[mt], bl[nt][0], bl[nt][1]);
                    mma16816(acc[mt][nt], al[mt], bh[nt][0], bh[nt][1]);
                }
        }
        __syncthreads();
    }

    #pragma unroll
    for (int mt = 0; mt < 2; ++mt)
        #pragma unroll
        for (int nt = 0; nt < 4; ++nt)
            #pragma unroll
            for (int c = 0; c < 4; ++c) {
                int row = wm * 32 + mt * 16 + g + (c >> 1) * 8;
                int col = wn * 32 + nt * 8 + 2 * tig + (c & 1);
                Ds[row * 68 + col] = acc[mt][nt][c];
            }
    __syncthreads();

    float* GX = GXptr(t);
    #pragma unroll
    for (int p = 0; p < 8; ++p) {
        int idx = tid + p * 256;
        int b = idx >> 4, o4 = idx & 15;
        float4 v = *(const float4*)(Ds + b * 68 + o4 * 4);
        float4 c = __ldg((const float4*)(bx + kk * G3 + o0 + o4 * 4));
        v.x += c.x; v.y += c.y; v.z += c.z; v.w += c.w;
        *(float4*)(GX + ((size_t)(kk * BB + b)) * G3 + o0 + o4 * 4) = v;
    }
}

// ======================================================================
// Full group barrier — used ONCE at init (8 blocks sharing (kk, B0)).
// ======================================================================
__device__ __forceinline__ void group_barrier(unsigned* ctr, unsigned target)
{
    __threadfence();
    __syncthreads();
    if (threadIdx.x == 0) {
        atomicAdd(ctr, 1u);
        while (volread(ctr) < target) { }
        __threadfence();
    }
    __syncthreads();
}

// ======================================================================
// Kernel 2: persistent recurrence with per-slice publish counters.
// 96 blocks x 256 thr. Block = (kk, J0 slice, B0 batch tile).
// h TRIPLE-buffered in global (bf16 hi/lo, L2 via stcg/ldcg).
// Quarter wk (warps 2wk,2wk+1) consumes only slices {2wk, 2wk+1}:
// waits on 2 counters, loads its 64-col A stripe, mma's immediately.
// Skew across the group is bounded by 1 step -> triple buffer is safe.
// ======================================================================
#define WP 264

__global__ __launch_bounds__(256, 1) void k_recur(const float* __restrict__ h0,
                                                  const float* __restrict__ Wh,
                                                  const float* __restrict__ bh)
{
    extern __shared__ unsigned short sm[];
    unsigned short* WhHi = sm;                   // [96][WP]
    unsigned short* WhLo = sm + 96 * WP;
    unsigned short* AHi  = sm + 2 * 96 * WP;     // [32][WP]
    unsigned short* ALo  = AHi + 32 * WP;
    float* FS  = (float*)(AHi + 2 * 32 * WP);
    float* CsB = FS;                             // [4][32][100] split-K partials
    float* Hex = FS + 4 * 3200;                  // [32][33] exact fp32 h piece
    float* bhs = FS + 4 * 3200 + 1056;           // [96]

    const int tid = threadIdx.x;
    const int blk = blockIdx.x;
    const int kk  = blk / 32;
    const int rem = blk - kk * 32;
    const int jsl = rem & 7;                     // own slice index (J0 = 32*jsl)
    const int J0  = jsl * 32;
    const int B0  = (rem >> 3) * 32;
    const int grp = kk * 4 + (rem >> 3);         // 0..11
    unsigned* gbar = &g_gbar[grp * 32];
    unsigned* cbase = &g_cnt[grp * 8 * 32];      // counter j at cbase[j*32]

    const int w = tid >> 5, lane = tid & 31;
    const int wk = w >> 1;           // 0..3 : K quarter (slices 2wk, 2wk+1)
    const int wn = w & 1;            // 0..1 : 48-col half
    const int qtid = tid & 63;       // thread index within quarter
    const int lr = lane & 15, lc = (lane >> 4) * 8;
    const int br = ((lane >> 4) & 1) * 8 + (lane & 7);
    const int bc = ((lane >> 3) & 1) * 8;
    const int cb = tid >> 3, cu = (tid & 7) * 4; // combine: (b, 4 units)

    // ---- init: resident Wh^T slice, split to bf16 hi/lo ----
    for (int q = tid; q < 96 * 256; q += 256) {
        int n = q >> 8, i = q & 255;
        int gG = n >> 5, j = n & 31;
        float v = __ldg(Wh + ((size_t)kk * HH + i) * G3 + gG * HH + J0 + j);
        unsigned short hi, lo; bsplit(v, hi, lo);
        WhHi[n * WP + i] = hi;
        WhLo[n * WP + i] = lo;
    }
    if (tid < 96)
        bhs[tid] = __ldg(bh + kk * G3 + (tid >> 5) * HH + J0 + (tid & 31));

    // ---- init: h0 -> exact smem piece + global bf16 buffer 0 ----
    {
        unsigned short hi4[4], lo4[4];
        #pragma unroll
        for (int e = 0; e < 4; ++e) {
            float v = __ldg(h0 + ((size_t)kk * BB + B0 + cb) * HH + J0 + cu + e);
            Hex[cb * 33 + cu + e] = v;
            bsplit(v, hi4[e], lo4[e]);
        }
        size_t o = ((size_t)kk * BB + B0 + cb) * HH + J0 + cu;
        __stcg((uint2*)(&g_Hh[0][0][0][0] + o), *(uint2*)hi4);
        __stcg((uint2*)(&g_Hl[0][0][0][0] + o), *(uint2*)lo4);
    }
    group_barrier(gbar, 8u);   // h0 published to the whole group

    for (int s = 0; s < TT; ++s) {
        const int cur = s % 3, nxt = (s + 1) % 3;
        const float* GX = GXptr(s);

        // gx prefetch (independent of h): 3 gates x 4 units for (cb, cu)
        float gx[3][4];
        #pragma unroll
        for (int gG = 0; gG < 3; ++gG) {
            float4 v = __ldg((const float4*)(
                GX + ((size_t)(kk * BB + B0 + cb)) * G3 + gG * HH + J0 + cu));
            gx[gG][0] = v.x; gx[gG][1] = v.y; gx[gG][2] = v.z; gx[gG][3] = v.w;
        }

        // ---- per-quarter wait: slices 2wk, 2wk+1 published version >= s ----
        {
            const unsigned* c0 = cbase + (2 * wk) * 32;
            const unsigned* c1 = cbase + (2 * wk + 1) * 32;
            unsigned us = (unsigned)s;
            while (volread(c0) < us) { }
            while (volread(c1) < us) { }
            __threadfence();   // acquire: order subsequent ldcg after the flag
        }

        // ---- per-quarter A-stripe load: 32 rows x cols [64wk, 64wk+64) ----
        const unsigned short* srcH = &g_Hh[cur][kk][0][0];
        const unsigned short* srcL = &g_Hl[cur][kk][0][0];
        #pragma unroll
        for (int p = 0; p < 4; ++p) {
            int idx = qtid + p * 64;             // 256 = 32 r x 8 c8
            int r = idx >> 3, c8 = idx & 7;
            int colg = wk * 64 + c8 * 8;
            size_t go = ((size_t)(B0 + r)) * HH + colg;
            *(uint4*)(AHi + r * WP + colg) = __ldcg((const uint4*)(srcH + go));
            *(uint4*)(ALo + r * WP + colg) = __ldcg((const uint4*)(srcL + go));
        }
        asm volatile("bar.sync %0, 64;" :: "r"(1 + wk) : "memory");

        // gh partial: warp covers m 0..31, n half (48), its K quarter (64)
        float acc[2][6][4];
        #pragma unroll
        for (int mt = 0; mt < 2; ++mt)
            #pragma unroll
            for (int nt = 0; nt < 6; ++nt)
                #pragma unroll
                for (int c = 0; c < 4; ++c) acc[mt][nt][c] = 0.f;

        #pragma unroll
        for (int kt = 0; kt < 4; ++kt) {
            int k0 = wk * 64 + kt * 16;
            uint32 ah[2][4], al[2][4];
            #pragma unroll
            for (int mt = 0; mt < 2; ++mt) {
                int R = mt * 16 + lr;
                ldsm4(ah[mt], AHi + R * WP + k0 + lc);
                ldsm4(al[mt], ALo + R * WP + k0 + lc);
            }
            uint32 bhf[6][2], blf[6][2];
            #pragma unroll
            for (int p = 0; p < 3; ++p) {
                uint32 r4[4];
                int R = wn * 48 + p * 16 + br;
                ldsm4(r4, WhHi + R * WP + k0 + bc);
                bhf[2*p][0] = r4[0]; bhf[2*p][1] = r4[1];
                bhf[2*p+1][0] = r4[2]; bhf[2*p+1][1] = r4[3];
                ldsm4(r4, WhLo + R * WP + k0 + bc);
                blf[2*p][0] = r4[0]; blf[2*p][1] = r4[1];
                blf[2*p+1][0] = r4[2]; blf[2*p+1][1] = r4[3];
            }
            #pragma unroll
            for (int mt = 0; mt < 2; ++mt)
                #pragma unroll
                for (int nt = 0; nt < 6; ++nt) {
                    mma16816(acc[mt][nt], ah[mt], bhf[nt][0], bhf[nt][1]);
                    mma16816(acc[mt][nt], ah[mt], blf[nt][0], blf[nt][1]);
                    mma16816(acc[mt][nt], al[mt], bhf[nt][0], bhf[nt][1]);
                }
        }

        // dump partials -> CsB[wk][b][n], pitch 100
        float* Cs = CsB + wk * 3200;
        #pragma unroll
        for (int mt = 0; mt < 2; ++mt)
            #pragma unroll
            for (int nt = 0; nt < 6; ++nt)
                #pragma unroll
                for (int c = 0; c < 4; ++c) {
                    int row = mt * 16 + (lane >> 2) + (c >> 1) * 8;
                    int col = wn * 48 + nt * 8 + 2 * (lane & 3) + (c & 1);
                    Cs[row * 100 + col] = acc[mt][nt][c];
                }
        __syncthreads();

        // combine: gates + state update for (cb, cu..cu+3)
        unsigned short hi4[4], lo4[4];
        #pragma unroll
        for (int e = 0; e < 4; ++e) {
            int u = cu + e;
            int base = cb * 100 + u;
            float Cr = CsB[base] + CsB[3200 + base] + CsB[6400 + base] + CsB[9600 + base];
            float Cz = CsB[base + 32] + CsB[3200 + base + 32]
                     + CsB[6400 + base + 32] + CsB[9600 + base + 32];
            float Cn = CsB[base + 64] + CsB[3200 + base + 64]
                     + CsB[6400 + base + 64] + CsB[9600 + base + 64];
            float r = 1.f / (1.f + __expf(-(gx[0][e] + Cr + bhs[u])));
            float z = 1.f / (1.f + __expf(-(gx[1][e] + Cz + bhs[32 + u])));
            float nh = Cn + bhs[64 + u];
            float n = tanhf(gx[2][e] + r * nh);
            float hold = Hex[cb * 33 + u];
            float hnew = (1.f - z) * n + z * hold;
            Hex[cb * 33 + u] = hnew;
            bsplit(hnew, hi4[e], lo4[e]);
            if (s == TT - 1)
                g_Hfin[kk][B0 + cb][J0 + u] = hnew;
        }
        {
            size_t o = ((size_t)kk * BB + B0 + cb) * HH + J0 + cu;
            __stcg((uint2*)(&g_Hh[nxt][0][0][0] + o), *(uint2*)hi4);
            __stcg((uint2*)(&g_Hl[nxt][0][0][0] + o), *(uint2*)lo4);
        }

        // publish h(s+1): release fence + single counter bump for own slice.
        __threadfence();
        __syncthreads();                  // also protects CsB reuse next step
        if (tid == 0 && s + 1 < TT)
            atomicAdd(cbase + jsl * 32, 1u);
    }

    // Reset counters so every graph replay starts clean (all blocks done).
    if (tid == 0) {
        unsigned old = atomicAdd(&g_done, 1u);
        if (old == NBLK - 1) {
            #pragma unroll
            for (int i = 0; i < 12; ++i) g_gbar[i * 32] = 0u;
            for (int i = 0; i < 96; ++i) g_cnt[i * 32] = 0u;
            g_done = 0u;
            __threadfence();
        }
    }
}

// ======================================================================
// Epilogue: out = elu(sum_k h @ W_fc + b_fc); feature = mean_b h
// ======================================================================
__global__ void k_fc(const float* __restrict__ Wfc, const float* __restrict__ bfc,
                     float* __restrict__ out)
{
    __shared__ float pooled[256];
    const int b = blockIdx.x, o = threadIdx.x;
    pooled[o] = g_Hfin[0][b][o] + g_Hfin[1][b][o] + g_Hfin[2][b][o];
    __syncthreads();
    float s = __ldg(bfc + o);
    #pragma unroll 8
    for (int j = 0; j < 256; ++j)
        s = fmaf(pooled[j], __ldg(Wfc + j * 256 + o), s);
    out[b * 256 + o] = (s > 0.f) ? s : expm1f(s);
}

__global__ void k_feat(float* __restrict__ outF)
{
    const int k = blockIdx.x, u = threadIdx.x;
    float s = 0.f;
    #pragma unroll 4
    for (int b = 0; b < 128; ++b) s += g_Hfin[k][b][u];
    outF[k * 256 + u] = s * (1.f / 128.f);
}

// ======================================================================
extern "C" void kernel_launch(void* const* d_in, const int* in_sizes, int n_in,
                              void* d_out, int out_size)
{
    const float* x   = (const float*)d_in[0];   // [128, 2048, 256]
    const float* h0  = (const float*)d_in[1];   // [1, 3, 128, 256]
    const float* Wx  = (const float*)d_in[2];   // [3, 256, 768]
    const float* Wh  = (const float*)d_in[3];   // [3, 256, 768]
    const float* bx  = (const float*)d_in[4];   // [3, 768]
    const float* bh  = (const float*)d_in[5];   // [3, 768]
    const float* Wfc = (const float*)d_in[6];   // [256, 256]
    const float* bfc = (const float*)d_in[7];   // [256]
    float* out = (float*)d_out;                 // out[128*256] ++ feature[3*256]

    const int smem_x = 2 * (128 + 64) * KPB * (int)sizeof(unsigned short); // 55296
    const int smem_r = 2 * (96 + 32) * WP * (int)sizeof(unsigned short)
                     + (4 * 3200 + 1056 + 96) * (int)sizeof(float);        // 190976
    cudaFuncSetAttribute(k_xgemm, cudaFuncAttributeMaxDynamicSharedMemorySize, smem_x);
    cudaFuncSetAttribute(k_recur, cudaFuncAttributeMaxDynamicSharedMemorySize, smem_r);

    k_split_x<<<TT, 256>>>(x);
    k_split_wx<<<3 * G3, 256>>>(Wx);
    k_xgemm<<<dim3(36, TT), 256, smem_x>>>(bx);
    k_recur<<<NBLK, 256, smem_r>>>(h0, Wh, bh);
    k_fc<<<128, 256>>>(Wfc, bfc, out);
    k_feat<<<3, 256>>>(out + 128 * 256);
    (void)in_sizes; (void)n_in; (void)out_size;
}